// round 17
// baseline (speedup 1.0000x reference)
#include <cuda_runtime.h>
#include <cuda_bf16.h>
#include <cuda_fp16.h>
#include <math.h>
#include <cstdint>

#define N 4096
#define D 256
#define NBB 64                        // 64-row/col blocks
#define NTILES3 2080                  // j>=i pairs of 64-blocks
#define GCTAS3 296                    // 2 CTAs/SM
#define PAIR_CAP (1u << 23)

// ---------------- device globals ----------------
__device__ __align__(16) __nv_bfloat16  g_normh[N * D]; // rows pre-swizzled: chunk c at c^(row&7)
__device__ __align__(16) __half         g_labh[N];      // labels as half (exact, <2048)
__device__ float    g_neg[N];
__device__ float    g_loss_f;
__device__ unsigned g_npair;
__device__ unsigned g_done;
__device__ unsigned g_pair_ij[PAIR_CAP];
__device__ float    g_pair_s[PAIR_CAP];

// ---------------- smem layout (~96.4 KB per 256-thread CTA -> 2/SM) ----------------
#define SMEM_A    0            // 64 rows x 512B = 32768
#define SMEM_B0   32768        // 32768
#define SMEM_B1   65536        // 32768
#define SMEM_MBA  98304
#define SMEM_MBB0 98312
#define SMEM_MBB1 98320
#define SMEM_LABI 98336        // 64 half = 128B
#define SMEM_LABJ 98464        // 64 half = 128B
#define SMEM_GT   98624

__device__ __forceinline__ uint32_t smem_u32(const void* p) {
    uint32_t a;
    asm("{ .reg .u64 t; cvta.to.shared.u64 t, %1; cvt.u32.u64 %0, t; }" : "=r"(a) : "l"(p));
    return a;
}
#define MBAR_INIT(mb, c)  asm volatile("mbarrier.init.shared.b64 [%0], %1;" :: "r"(mb), "r"(c) : "memory")
#define MBAR_EXPECT(mb, tx) asm volatile("mbarrier.arrive.expect_tx.shared.b64 _, [%0], %1;" :: "r"(mb), "r"(tx) : "memory")
#define BULK_LD(dst, src, sz, mb) \
    asm volatile("cp.async.bulk.shared::cta.global.mbarrier::complete_tx::bytes [%0], [%1], %2, [%3];" \
        :: "r"(dst), "l"(src), "r"(sz), "r"(mb) : "memory")

__device__ __forceinline__ void mbar_wait(uint32_t mb, uint32_t parity) {
    uint32_t done;
    asm volatile("{ .reg .pred p; mbarrier.try_wait.parity.acquire.cta.shared::cta.b64 p, [%1], %2; selp.b32 %0, 1, 0, p; }"
                 : "=r"(done) : "r"(mb), "r"(parity) : "memory");
    if (!done) {
        asm volatile("{ .reg .pred P1; W%=: mbarrier.try_wait.parity.acquire.cta.shared::cta.b64 P1, [%0], %1, 0x989680; @P1 bra.uni DN%=; bra.uni W%=; DN%=: }"
                     :: "r"(mb), "r"(parity) : "memory");
    }
}

#define LDSM4(r, a) \
    asm volatile("ldmatrix.sync.aligned.m8n8.x4.shared.b16 {%0,%1,%2,%3}, [%4];" \
        : "=r"((r)[0]), "=r"((r)[1]), "=r"((r)[2]), "=r"((r)[3]) : "r"(a))
#define LDSM4T(r, a) \
    asm volatile("ldmatrix.sync.aligned.m8n8.x4.trans.shared.b16 {%0,%1,%2,%3}, [%4];" \
        : "=r"((r)[0]), "=r"((r)[1]), "=r"((r)[2]), "=r"((r)[3]) : "r"(a))
#define MMA16816(d, a, b0_, b1_) \
    asm volatile("mma.sync.aligned.m16n8k16.row.col.f32.bf16.bf16.f32 " \
        "{%0,%1,%2,%3}, {%4,%5,%6,%7}, {%8,%9}, {%0,%1,%2,%3};" \
        : "+f"((d)[0]), "+f"((d)[1]), "+f"((d)[2]), "+f"((d)[3]) \
        : "r"((a)[0]), "r"((a)[1]), "r"((a)[2]), "r"((a)[3]), "r"(b0_), "r"(b1_))

// tiles before row band bi (row-major, bj from bi..63): 64*bi - bi*(bi-1)/2
__device__ __forceinline__ int tile_base3(int bi) { return 64 * bi - (bi * (bi - 1)) / 2; }

// ---------------- kernels ----------------
__global__ __launch_bounds__(256) void k_norm(const float* __restrict__ x,
                                              const void* __restrict__ labels) {
    __shared__ int s_nz;
    const int tid = threadIdx.x, wid = tid >> 5, l = tid & 31;
    if (tid == 0) {
        s_nz = 0;
        if (blockIdx.x == 0) { g_npair = 0u; g_done = 0u; g_loss_f = 0.f; }
    }
    __syncthreads();
    const int* l32 = (const int*)labels;
    if (tid < 128 && l32[2 * tid + 1] != 0) atomicOr(&s_nz, 1);
    __syncthreads();
    const bool is64 = (s_nz == 0);

    const int row = blockIdx.x * 8 + wid;
    if (row < N) {
        float4 v0 = *(const float4*)&x[row * D + l * 8];
        float4 v1 = *(const float4*)&x[row * D + l * 8 + 4];
        float sq = v0.x * v0.x + v0.y * v0.y + v0.z * v0.z + v0.w * v0.w
                 + v1.x * v1.x + v1.y * v1.y + v1.z * v1.z + v1.w * v1.w;
        #pragma unroll
        for (int o = 16; o > 0; o >>= 1) sq += __shfl_xor_sync(0xffffffffu, sq, o);
        float inv = 1.0f / fmaxf(sqrtf(sq), 1e-12f);
        __nv_bfloat162 h0 = __floats2bfloat162_rn(v0.x * inv, v0.y * inv);
        __nv_bfloat162 h1 = __floats2bfloat162_rn(v0.z * inv, v0.w * inv);
        __nv_bfloat162 h2 = __floats2bfloat162_rn(v1.x * inv, v1.y * inv);
        __nv_bfloat162 h3 = __floats2bfloat162_rn(v1.z * inv, v1.w * inv);
        uint4 pk;
        pk.x = *(uint32_t*)&h0; pk.y = *(uint32_t*)&h1;
        pk.z = *(uint32_t*)&h2; pk.w = *(uint32_t*)&h3;
        int cs = l ^ (row & 7);
        *(uint4*)&g_normh[row * D + cs * 8] = pk;
        if (l == 0) {
            int lv = is64 ? (int)((const long long*)labels)[row] : l32[row];
            g_labh[row] = __float2half((float)lv);
            g_neg[row] = 0.f;
        }
    }
}

// Persistent bf16 mma.sync GEMM over 64x64 tiles (bj >= bi), row-major order.
// A = row band (cached); B double-buffered with next-tile prefetch. 2 CTAs/SM.
__global__ __launch_bounds__(256, 2) void k_gemm() {
    extern __shared__ char smem[];
    const int tid = threadIdx.x, wid = tid >> 5, l = tid & 31;
    const int wm = wid & 3, wn = wid >> 2;            // warp tile 16x32
    const uint32_t sb = smem_u32(smem);
    const __half* labih = (const __half*)(smem + SMEM_LABI);
    const half2* labjh2 = (const half2*)(smem + SMEM_LABJ);

    if (tid == 0) {
        MBAR_INIT(sb + SMEM_MBA, 1);
        MBAR_INIT(sb + SMEM_MBB0, 1);
        MBAR_INIT(sb + SMEM_MBB1, 1);
    }
    __syncthreads();

    const int s = (int)(((long)blockIdx.x * NTILES3) / GCTAS3);
    const int e = (int)(((long)(blockIdx.x + 1) * NTILES3) / GCTAS3);
    if (s >= e) return;

    int bi = 0;
    while (tile_base3(bi + 1) <= s) bi++;
    int bjj = bi + (s - tile_base3(bi));

    const uint32_t bbuf[2] = { (uint32_t)SMEM_B0, (uint32_t)SMEM_B1 };
    const uint32_t bmb[2]  = { (uint32_t)SMEM_MBB0, (uint32_t)SMEM_MBB1 };
    int bph[2] = {0, 0};
    int aph = 0;
    int cur = 0;
    bool waitA = true;

    // prologue: issue A band + first B
    if (tid == 0) {
        MBAR_EXPECT(sb + SMEM_MBA, 32768u);
        #pragma unroll
        for (int q = 0; q < 4; q++)
            BULK_LD(sb + SMEM_A + q * 8192,
                    (const char*)&g_normh[(size_t)(bi * 64) * D] + q * 8192, 8192u, sb + SMEM_MBA);
        MBAR_EXPECT(sb + bmb[0], 32768u);
        #pragma unroll
        for (int q = 0; q < 4; q++)
            BULK_LD(sb + bbuf[0] + q * 8192,
                    (const char*)&g_normh[(size_t)(bjj * 64) * D] + q * 8192, 8192u, sb + bmb[0]);
    }
    int curA = bi;

    const half2 SC = __float2half2_rn(2.8853900817779268f);   // 2*log2(e)

    for (int t = s; t < e; t++) {
        const bool diag = (bi == bjj);
        const int iBase = bi * 64;
        const int jBase = bjj * 64;

        __syncthreads();   // previous compute/epilogue complete

        if (bi != curA) {  // rare band transition: exposed A reload
            if (tid == 0) {
                MBAR_EXPECT(sb + SMEM_MBA, 32768u);
                #pragma unroll
                for (int q = 0; q < 4; q++)
                    BULK_LD(sb + SMEM_A + q * 8192,
                            (const char*)&g_normh[(size_t)iBase * D] + q * 8192, 8192u, sb + SMEM_MBA);
            }
            curA = bi;
            waitA = true;
        }
        // stage labels for this tile
        if (tid < 32) ((unsigned*)(smem + SMEM_LABI))[tid] = ((const unsigned*)&g_labh[iBase])[tid];
        else if (tid < 64) ((unsigned*)(smem + SMEM_LABJ))[tid - 32] = ((const unsigned*)&g_labh[jBase])[tid - 32];

        mbar_wait(sb + bmb[cur], bph[cur]); bph[cur] ^= 1;
        if (waitA) { mbar_wait(sb + SMEM_MBA, aph); aph ^= 1; waitA = false; }
        __syncthreads();   // data + labels visible

        // prefetch next tile's B into the other buffer (safe: consumers done)
        if (t + 1 < e && tid == 0) {
            int bi2 = bi, bjj2 = bjj + 1;
            if (bjj2 == NBB) { bi2++; bjj2 = bi2; }
            const int nb = cur ^ 1;
            MBAR_EXPECT(sb + bmb[nb], 32768u);
            #pragma unroll
            for (int q = 0; q < 4; q++)
                BULK_LD(sb + bbuf[nb] + q * 8192,
                        (const char*)&g_normh[(size_t)(bjj2 * 64) * D] + q * 8192, 8192u, sb + bmb[nb]);
        }

        // ---- compute: 64x64 tile, warp tile 16x32 ----
        float acc[4][4];
        #pragma unroll
        for (int nt = 0; nt < 4; nt++)
            #pragma unroll
            for (int ee = 0; ee < 4; ee++) acc[nt][ee] = 0.f;

        const int row_a = wm * 16 + (l & 15);
        const uint32_t abase = sb + SMEM_A + (uint32_t)row_a * 512;
        const int rxa = row_a & 7;
        const int hia = (l >> 4);
        const int row_b = wn * 32 + (l & 7) + ((l & 16) ? 8 : 0);
        const uint32_t bbase = sb + bbuf[cur] + (uint32_t)row_b * 512;
        const int rxb = row_b & 7;
        const int hib = (l >> 3) & 1;

        #pragma unroll
        for (int ks = 0; ks < 16; ks++) {
            const uint32_t ka = (uint32_t)(((ks * 2 + hia) ^ rxa) << 4);
            const uint32_t kb = (uint32_t)(((ks * 2 + hib) ^ rxb) << 4);
            uint32_t A0[4];
            LDSM4(A0, abase + ka);
            #pragma unroll
            for (int p = 0; p < 2; p++) {
                uint32_t Bt[4];
                LDSM4T(Bt, bbase + (uint32_t)p * 8192 + kb);
                MMA16816(acc[2 * p],     A0, Bt[0], Bt[1]);
                MMA16816(acc[2 * p + 1], A0, Bt[2], Bt[3]);
            }
        }

        // ---- epilogue: neg sums (label + triangle masked) + pair emission ----
        half2 cneg2[4];
        #pragma unroll
        for (int nt = 0; nt < 4; nt++) cneg2[nt] = __float2half2_rn(0.f);

        #pragma unroll
        for (int half_ = 0; half_ < 2; half_++) {
            const int row_local = wm * 16 + half_ * 8 + (l >> 2);
            const int gi = iBase + row_local;
            const half2 li2 = __half2half2(labih[row_local]);
            half2 t2 = __float2half2_rn(0.f);
            #pragma unroll
            for (int nt = 0; nt < 4; nt++) {
                const int col0 = jBase + wn * 32 + nt * 8 + (l & 3) * 2;
                half2 h = __floats2half2_rn(acc[nt][half_ * 2], acc[nt][half_ * 2 + 1]);
                half2 ex = h2exp2(__hmul2(h, SC));
                half2 m2 = __heq2(labjh2[wn * 16 + nt * 4 + (l & 3)], li2);
                half2 nx = __hsub2(ex, __hmul2(ex, m2));
                if (diag) {
                    half2 vm = __floats2half2_rn(gi < col0 ? 1.f : 0.f, gi < col0 + 1 ? 1.f : 0.f);
                    nx = __hmul2(nx, vm);
                }
                t2 = __hadd2(t2, nx);
                cneg2[nt] = __hadd2(cneg2[nt], nx);
                unsigned mu = *(unsigned*)&m2;
                if (mu) {
                    if ((mu & 0xFFFFu) && gi < col0) {
                        unsigned gp = atomicAdd(&g_npair, 1u);
                        if (gp < PAIR_CAP) { g_pair_ij[gp] = ((unsigned)gi << 12) | (unsigned)col0; g_pair_s[gp] = acc[nt][half_ * 2]; }
                    }
                    if ((mu >> 16) && gi < col0 + 1) {
                        unsigned gp = atomicAdd(&g_npair, 1u);
                        if (gp < PAIR_CAP) { g_pair_ij[gp] = ((unsigned)gi << 12) | (unsigned)(col0 + 1); g_pair_s[gp] = acc[nt][half_ * 2 + 1]; }
                    }
                }
            }
            float2 f = __half22float2(t2);
            float tt = f.x + f.y;
            tt += __shfl_xor_sync(0xffffffffu, tt, 1);
            tt += __shfl_xor_sync(0xffffffffu, tt, 2);
            if ((l & 3) == 0) atomicAdd(&g_neg[gi], tt);
        }
        // column (transpose-direction) sums
        #pragma unroll
        for (int nt = 0; nt < 4; nt++) {
            uint32_t v = *(uint32_t*)&cneg2[nt];
            #pragma unroll
            for (int m = 4; m <= 16; m <<= 1) {
                uint32_t o = __shfl_xor_sync(0xffffffffu, v, m);
                half2 hv = *(half2*)&v, ho = *(half2*)&o;
                hv = __hadd2(hv, ho);
                v = *(uint32_t*)&hv;
            }
            if (l < 4) {
                float2 fc = __half22float2(*(half2*)&v);
                int c0 = wn * 32 + nt * 8 + l * 2;
                atomicAdd(&g_neg[jBase + c0], fc.x);
                atomicAdd(&g_neg[jBase + c0 + 1], fc.y);
            }
        }

        // advance
        bjj++;
        if (bjj == NBB) { bi++; bjj = bi; }
        cur ^= 1;
    }
}

// Streaming loss over (i,j,s) records; last block finalizes.
__global__ __launch_bounds__(256) void k_loss(float* __restrict__ out) {
    unsigned np = g_npair;
    if (np > PAIR_CAP) np = PAIR_CAP;
    float lsum = 0.f;
    for (unsigned p = blockIdx.x * 256 + threadIdx.x; p < np; p += gridDim.x * 256) {
        unsigned ij = g_pair_ij[p];
        int i = (int)(ij >> 12);
        int j = (int)(ij & 0xfffu);
        float s = g_pair_s[p];
        float e = __expf(2.0f * s);
        lsum += logf(e + g_neg[i]) + logf(e + g_neg[j]) - 4.0f * s;
    }
    #pragma unroll
    for (int o = 16; o > 0; o >>= 1) lsum += __shfl_down_sync(0xffffffffu, lsum, o);
    __shared__ float sd[8];
    if ((threadIdx.x & 31) == 0) sd[threadIdx.x >> 5] = lsum;
    __syncthreads();
    if (threadIdx.x == 0) {
        float L = sd[0] + sd[1] + sd[2] + sd[3] + sd[4] + sd[5] + sd[6] + sd[7];
        if (L != 0.f) atomicAdd(&g_loss_f, L);
        __threadfence();
        unsigned d = atomicAdd(&g_done, 1u);
        if (d == gridDim.x - 1) {
            float total = atomicAdd(&g_loss_f, 0.f);
            out[0] = np ? (total / (float)(2u * np)) : 0.f;
        }
    }
}

// ---------------- launch ----------------
extern "C" void kernel_launch(void* const* d_in, const int* in_sizes, int n_in,
                              void* d_out, int out_size) {
    const float* x = (const float*)d_in[0];
    const void* labels = d_in[1];

    static bool attr_done = false;
    if (!attr_done) {
        cudaFuncSetAttribute(k_gemm, cudaFuncAttributeMaxDynamicSharedMemorySize, SMEM_GT);
        attr_done = true;
    }

    k_norm<<<512, 256>>>(x, labels);
    k_gemm<<<GCTAS3, 256, SMEM_GT>>>();
    k_loss<<<128, 256>>>((float*)d_out);
}